// round 3
// baseline (speedup 1.0000x reference)
#include <cuda_runtime.h>
#include <cstdint>

#define NN 2048
#define BS 256
#define THRESH 0.3f
#define OVERLAP 0.5f
#define MCAP 1024                 // mask-NMS path supports up to 1024 valid items
#define WMAX (MCAP / 64)          // 16 words per mask row
#define MASK_BYTES (MCAP * WMAX * 8)  // 128 KB dynamic smem

__global__ __launch_bounds__(BS) void det_kernel(
    const float* __restrict__ loc,    // (8,2048,2)
    const float* __restrict__ cls,    // (8,2048,5)
    const float* __restrict__ dflt,   // (2048,2)
    float* __restrict__ out)          // (8,4,2048,3)
{
    extern __shared__ unsigned long long s_mask[];   // [MCAP][W] suppression rows
    __shared__ float2 s_box[NN];                     // decoded (start,end), original order
    __shared__ float  s_score[NN];
    __shared__ unsigned long long s_key[NN];         // sort keys (compacted)
    __shared__ float2 s_sbox[MCAP];                  // boxes in sorted order
    __shared__ unsigned char s_keep[NN];             // keep flag, SORTED order
    __shared__ unsigned char s_keep_orig[NN];        // keep flag, original order
    __shared__ unsigned long long s_keepbits[32];
    __shared__ int s_m;

    const int b = blockIdx.x >> 2;
    const int c = blockIdx.x & 3;     // class index into scores[1..4]
    const int tid = threadIdx.x;

    if (tid == 0) s_m = 0;
    __syncthreads();

    const float* locb = loc + (size_t)b * NN * 2;
    const float* clsb = cls + (size_t)b * NN * 5;

    // ---- decode + softmax + compact valid keys ----
    for (int n = tid; n < NN; n += BS) {
        float dc = dflt[2 * n], dw = dflt[2 * n + 1];
        float l0 = locb[2 * n], l1 = locb[2 * n + 1];
        float ctr = dc + l0 * dw;
        float w   = dw * expf(l1);
        s_box[n] = make_float2(ctr - 0.5f * w, ctr + 0.5f * w);

        float x0 = clsb[5 * n + 0];
        float x1 = clsb[5 * n + 1];
        float x2 = clsb[5 * n + 2];
        float x3 = clsb[5 * n + 3];
        float x4 = clsb[5 * n + 4];
        float mx = fmaxf(fmaxf(fmaxf(x0, x1), fmaxf(x2, x3)), x4);
        float sum = expf(x0 - mx) + expf(x1 - mx) + expf(x2 - mx)
                  + expf(x3 - mx) + expf(x4 - mx);
        float sc = expf(clsb[5 * n + 1 + c] - mx) / sum;
        s_score[n] = sc;
        s_keep[n] = 0;
        s_keep_orig[n] = 0;

        if (sc > THRESH) {
            int slot = atomicAdd(&s_m, 1);
            // (score_bits, 2047-n): descending u64 sort == stable argsort(-score)
            s_key[slot] = ((unsigned long long)__float_as_uint(sc) << 32)
                        | (unsigned int)(2047 - n);
        }
    }
    __syncthreads();
    const int M = s_m;

    // ---- pad to pow2 and bitonic-sort descending ----
    int P = 1;
    while (P < M) P <<= 1;
    for (int j = M + tid; j < P; j += BS) s_key[j] = 0ull;  // pads sort last
    __syncthreads();

    if (M > 1) {
        for (int k = 2; k <= P; k <<= 1) {
            for (int j = k >> 1; j > 0; j >>= 1) {
                for (int t = tid; t < (P >> 1); t += BS) {
                    int i = ((t & ~(j - 1)) << 1) | (t & (j - 1));
                    int l = i | j;
                    unsigned long long a  = s_key[i];
                    unsigned long long bb = s_key[l];
                    bool desc = ((i & k) == 0);
                    if ((a < bb) == desc) { s_key[i] = bb; s_key[l] = a; }
                }
                __syncthreads();
            }
        }
    }

    // ---- gather boxes into sorted order (mask path) ----
    const int Mc = (M < MCAP) ? M : MCAP;
    for (int j = tid; j < Mc; j += BS) {
        int n = 2047 - (int)(unsigned int)s_key[j];
        s_sbox[j] = s_box[n];
    }
    __syncthreads();

    if (M > 0 && M <= MCAP) {
        // ==== mask-based NMS ====
        const int W = (M + 63) >> 6;

        // build suppression rows: bit b of word w of row i set iff iou(i, w*64+b) > 0.5, j > i
        for (int task = tid; task < M * W; task += BS) {
            int i = task / W;
            int w = task - i * W;
            int base = w << 6;
            unsigned long long m = 0ull;
            if (base + 63 > i) {
                float2 bi = s_sbox[i];
                float li = bi.y - bi.x;
                int lim = M - base; if (lim > 64) lim = 64;
                for (int bb = 0; bb < lim; bb++) {
                    int j = base + bb;
                    if (j <= i) continue;
                    float2 bj = s_sbox[j];
                    float inter = fmaxf(fminf(bi.y, bj.y) - fmaxf(bi.x, bj.x), 0.0f);
                    float uni = li + (bj.y - bj.x) - inter;
                    float iou = inter / fmaxf(uni, 1e-12f);
                    if (iou > OVERLAP) m |= (1ull << bb);
                }
            }
            s_mask[task] = m;
        }
        __syncthreads();

        // warp-cooperative scan: lane l owns removal word l
        if (tid < 32) {
            const unsigned FULL = 0xffffffffu;
            int lane = tid;
            unsigned long long remv = 0ull;
            for (int g = 0; g < W; g++) {
                unsigned long long r = __shfl_sync(FULL, remv, g);
                unsigned long long keptbits = 0ull;
                if (lane == g) {
                    int base = g << 6;
                    int lim = M - base; if (lim > 64) lim = 64;
                    for (int bb = 0; bb < lim; bb++) {
                        if (!((r >> bb) & 1ull)) {
                            keptbits |= (1ull << bb);
                            r |= s_mask[(size_t)(base + bb) * W + g];
                        }
                    }
                }
                keptbits = __shfl_sync(FULL, keptbits, g);
                if (lane < W) {
                    unsigned long long kb = keptbits;
                    int base = g << 6;
                    while (kb) {
                        int bb = __ffsll((long long)kb) - 1;
                        kb &= kb - 1;
                        remv |= s_mask[(size_t)(base + bb) * W + lane];
                    }
                }
                if (lane == 0) s_keepbits[g] = keptbits;
            }
        }
        __syncthreads();
        for (int j = tid; j < M; j += BS)
            s_keep[j] = (unsigned char)((s_keepbits[j >> 6] >> (j & 63)) & 1ull);
        __syncthreads();
    } else if (M > MCAP) {
        // ==== fallback: greedy serial NMS (correctness safety net) ====
        for (int j = tid; j < M; j += BS) s_keep[j] = 1;
        __syncthreads();
        for (int i = 0; i < M; i++) {
            if (s_keep[i]) {
                int ni = 2047 - (int)(unsigned int)s_key[i];
                float2 bi = s_box[ni];
                float li = bi.y - bi.x;
                for (int j = i + 1 + tid; j < M; j += BS) {
                    if (!s_keep[j]) continue;
                    int nj = 2047 - (int)(unsigned int)s_key[j];
                    float2 bj = s_box[nj];
                    float inter = fmaxf(fminf(bi.y, bj.y) - fmaxf(bi.x, bj.x), 0.0f);
                    float uni = li + (bj.y - bj.x) - inter;
                    if (inter / fmaxf(uni, 1e-12f) > OVERLAP) s_keep[j] = 0;
                }
            }
            __syncthreads();
        }
    }

    // ---- scatter keep to original order ----
    for (int j = tid; j < M; j += BS) {
        if (s_keep[j]) {
            int n = 2047 - (int)(unsigned int)s_key[j];
            s_keep_orig[n] = 1;
        }
    }
    __syncthreads();

    // ---- output (in_range applied AFTER NMS, matching reference) ----
    float* ob = out + (size_t)blockIdx.x * NN * 3;
    for (int n = tid; n < NN; n += BS) {
        float2 bx = s_box[n];
        bool kp = s_keep_orig[n] && (bx.x > -10.0f) && (bx.y < 10.0f);
        ob[3 * n + 0] = kp ? bx.x : 0.0f;
        ob[3 * n + 1] = kp ? bx.y : 0.0f;
        ob[3 * n + 2] = kp ? s_score[n] : 0.0f;
    }
}

extern "C" void kernel_launch(void* const* d_in, const int* in_sizes, int n_in,
                              void* d_out, int out_size) {
    const float* loc  = (const float*)d_in[0];  // (8,2048,2)
    const float* cls  = (const float*)d_in[1];  // (8,2048,5)
    const float* dflt = (const float*)d_in[2];  // (2048,2)
    float* out = (float*)d_out;                 // (8,4,2048,3)
    cudaFuncSetAttribute(det_kernel, cudaFuncAttributeMaxDynamicSharedMemorySize,
                         MASK_BYTES);
    det_kernel<<<32, BS, MASK_BYTES>>>(loc, cls, dflt, out);
}

// round 4
// speedup vs baseline: 1.1469x; 1.1469x over previous
#include <cuda_runtime.h>
#include <cstdint>

#define NN 2048
#define BS 256
#define R  8              // owned slots per thread (BS*R = NN)
#define NW (NN / 64)      // alive-bitmask words
#define THRESH 0.3f
#define OVERLAP 0.5f

__global__ __launch_bounds__(BS) void det_kernel(
    const float* __restrict__ loc,    // (8,2048,2)
    const float* __restrict__ cls,    // (8,2048,5)
    const float* __restrict__ dflt,   // (2048,2)
    float* __restrict__ out)          // (8,4,2048,3)
{
    __shared__ float2 s_box[NN];                  // decoded boxes, original order
    __shared__ float  s_score[NN];
    __shared__ unsigned long long s_key[NN];      // compacted+sorted keys
    __shared__ unsigned long long s_alive[NW];    // alive bitmask, sorted order
    __shared__ unsigned char s_keep_orig[NN];
    __shared__ int s_m;
    __shared__ int s_cur;
    __shared__ float2 s_bi;

    const int b = blockIdx.x >> 2;
    const int c = blockIdx.x & 3;     // class index into scores[1..4]
    const int tid = threadIdx.x;

    if (tid == 0) s_m = 0;
    __syncthreads();

    const float* locb = loc + (size_t)b * NN * 2;
    const float* clsb = cls + (size_t)b * NN * 5;

    // ---- decode + softmax + compact valid keys ----
    for (int n = tid; n < NN; n += BS) {
        float dc = dflt[2 * n], dw = dflt[2 * n + 1];
        float l0 = locb[2 * n], l1 = locb[2 * n + 1];
        float ctr = dc + l0 * dw;
        float w   = dw * expf(l1);
        s_box[n] = make_float2(ctr - 0.5f * w, ctr + 0.5f * w);

        float x0 = clsb[5 * n + 0];
        float x1 = clsb[5 * n + 1];
        float x2 = clsb[5 * n + 2];
        float x3 = clsb[5 * n + 3];
        float x4 = clsb[5 * n + 4];
        float mx = fmaxf(fmaxf(fmaxf(x0, x1), fmaxf(x2, x3)), x4);
        float sum = expf(x0 - mx) + expf(x1 - mx) + expf(x2 - mx)
                  + expf(x3 - mx) + expf(x4 - mx);
        float sc = expf(clsb[5 * n + 1 + c] - mx) / sum;
        s_score[n] = sc;
        s_keep_orig[n] = 0;

        if (sc > THRESH) {
            int slot = atomicAdd(&s_m, 1);
            // (score_bits, 2047-n): descending u64 sort == stable argsort(-score)
            s_key[slot] = ((unsigned long long)__float_as_uint(sc) << 32)
                        | (unsigned int)(2047 - n);
        }
    }
    __syncthreads();
    const int M = s_m;

    // ---- pad valid keys to pow2 and bitonic-sort descending ----
    int P = 1;
    while (P < M) P <<= 1;
    for (int j = M + tid; j < P; j += BS) s_key[j] = 0ull;
    __syncthreads();

    if (M > 1) {
        for (int k = 2; k <= P; k <<= 1) {
            for (int j = k >> 1; j > 0; j >>= 1) {
                for (int t = tid; t < (P >> 1); t += BS) {
                    int i = ((t & ~(j - 1)) << 1) | (t & (j - 1));
                    int l = i | j;
                    unsigned long long a  = s_key[i];
                    unsigned long long bb = s_key[l];
                    bool desc = ((i & k) == 0);
                    if ((a < bb) == desc) { s_key[i] = bb; s_key[l] = a; }
                }
                __syncthreads();
            }
        }
    }

    // ---- init alive bitmask (bits 0..M-1 set) ----
    for (int w = tid; w < NW; w += BS) {
        int base = w << 6;
        unsigned long long word;
        if (base + 64 <= M)      word = ~0ull;
        else if (base >= M)      word = 0ull;
        else                     word = (~0ull) >> (64 - (M - base));
        s_alive[w] = word;
    }

    // ---- load owned sorted items into registers ----
    float2 bx[R];
    unsigned int aliveMask = 0;
    #pragma unroll
    for (int r = 0; r < R; r++) {
        int j = tid + r * BS;
        if (j < M) {
            int n = 2047 - (int)(unsigned int)s_key[j];
            bx[r] = s_box[n];
            aliveMask |= (1u << r);
        } else {
            bx[r] = make_float2(0.0f, 0.0f);
        }
    }

    // ---- greedy NMS iterating over KEPT items only ----
    int cur = -1;
    for (;;) {
        __syncthreads();   // make prior suppression atomicAnds visible to finder
        if (tid == 0) {
            int nxt = -1;
            int start = cur + 1;
            if (start < M) {
                int w = start >> 6;
                unsigned long long word = s_alive[w] & ((~0ull) << (start & 63));
                for (;;) {
                    if (word) { nxt = (w << 6) + __ffsll((long long)word) - 1; break; }
                    if (((++w) << 6) >= M) break;
                    word = s_alive[w];
                }
            }
            s_cur = nxt;
            if (nxt >= 0) {
                int n = 2047 - (int)(unsigned int)s_key[nxt];
                s_bi = s_box[n];
            }
        }
        __syncthreads();
        const int i = s_cur;
        if (i < 0) break;
        const float2 bi = s_bi;
        const float li = bi.y - bi.x;

        #pragma unroll
        for (int r = 0; r < R; r++) {
            int j = tid + r * BS;
            if ((aliveMask >> r & 1u) && j > i) {
                float2 bj = bx[r];
                float inter = fmaxf(fminf(bi.y, bj.y) - fmaxf(bi.x, bj.x), 0.0f);
                float uni = li + (bj.y - bj.x) - inter;
                float iou = inter / fmaxf(uni, 1e-12f);
                if (iou > OVERLAP) {
                    aliveMask &= ~(1u << r);
                    atomicAnd(&s_alive[j >> 6], ~(1ull << (j & 63)));
                }
            }
        }
        cur = i;
    }

    // ---- scatter final keep flags to original order ----
    #pragma unroll
    for (int r = 0; r < R; r++) {
        int j = tid + r * BS;
        if (j < M && (aliveMask >> r & 1u)) {
            int n = 2047 - (int)(unsigned int)s_key[j];
            s_keep_orig[n] = 1;
        }
    }
    __syncthreads();

    // ---- output (in_range applied AFTER NMS, matching reference) ----
    float* ob = out + (size_t)blockIdx.x * NN * 3;
    for (int n = tid; n < NN; n += BS) {
        float2 bxo = s_box[n];
        bool kp = s_keep_orig[n] && (bxo.x > -10.0f) && (bxo.y < 10.0f);
        ob[3 * n + 0] = kp ? bxo.x : 0.0f;
        ob[3 * n + 1] = kp ? bxo.y : 0.0f;
        ob[3 * n + 2] = kp ? s_score[n] : 0.0f;
    }
}

extern "C" void kernel_launch(void* const* d_in, const int* in_sizes, int n_in,
                              void* d_out, int out_size) {
    const float* loc  = (const float*)d_in[0];  // (8,2048,2)
    const float* cls  = (const float*)d_in[1];  // (8,2048,5)
    const float* dflt = (const float*)d_in[2];  // (2048,2)
    float* out = (float*)d_out;                 // (8,4,2048,3)
    det_kernel<<<32, BS>>>(loc, cls, dflt, out);
}

// round 7
// speedup vs baseline: 1.6135x; 1.4068x over previous
#include <cuda_runtime.h>
#include <cstdint>

#define NN 2048
#define BS 256
#define THRESH 0.3f
#define OVERLAP 0.5f
#define MCAP 1024                         // Jacobi path handles M <= 1024
#define KW (MCAP / 64)                    // 16 keep-mask words
#define MASK_BYTES (MCAP * KW * 8)        // 128 KB dynamic smem

__global__ __launch_bounds__(BS) void det_kernel(
    const float* __restrict__ loc,    // (8,2048,2)
    const float* __restrict__ cls,    // (8,2048,5)
    const float* __restrict__ dflt,   // (2048,2)
    float* __restrict__ out)          // (8,4,2048,3)
{
    extern __shared__ unsigned long long s_sup[];  // [M][W] suppression rows
    __shared__ float2 s_box[NN];                   // decoded boxes, original order
    __shared__ float  s_score[NN];
    __shared__ unsigned long long s_key[NN];       // compacted + sorted keys
    __shared__ float2 s_sbox[NN];                  // boxes, sorted order
    __shared__ unsigned long long s_keep[2][KW];
    __shared__ unsigned char s_keep_sorted[NN];    // final keep (fallback path)
    __shared__ unsigned char s_keep_orig[NN];
    __shared__ int s_m, s_changed;

    const int b = blockIdx.x >> 2;
    const int c = blockIdx.x & 3;     // class index into scores[1..4]
    const int tid = threadIdx.x;

    if (tid == 0) s_m = 0;
    __syncthreads();

    const float* locb = loc + (size_t)b * NN * 2;
    const float* clsb = cls + (size_t)b * NN * 5;

    // ---- decode + softmax + compact valid keys ----
    for (int n = tid; n < NN; n += BS) {
        float dc = dflt[2 * n], dw = dflt[2 * n + 1];
        float l0 = locb[2 * n], l1 = locb[2 * n + 1];
        float ctr = dc + l0 * dw;
        float w   = dw * expf(l1);
        s_box[n] = make_float2(ctr - 0.5f * w, ctr + 0.5f * w);

        float x0 = clsb[5 * n + 0];
        float x1 = clsb[5 * n + 1];
        float x2 = clsb[5 * n + 2];
        float x3 = clsb[5 * n + 3];
        float x4 = clsb[5 * n + 4];
        float mx = fmaxf(fmaxf(fmaxf(x0, x1), fmaxf(x2, x3)), x4);
        float sum = expf(x0 - mx) + expf(x1 - mx) + expf(x2 - mx)
                  + expf(x3 - mx) + expf(x4 - mx);
        float sc = expf(clsb[5 * n + 1 + c] - mx) / sum;
        s_score[n] = sc;
        s_keep_orig[n] = 0;

        if (sc > THRESH) {
            int slot = atomicAdd(&s_m, 1);
            // (score_bits, 2047-n): descending u64 sort == stable argsort(-score)
            s_key[slot] = ((unsigned long long)__float_as_uint(sc) << 32)
                        | (unsigned int)(2047 - n);
        }
    }
    __syncthreads();
    const int M = s_m;

    // ---- pad valid keys to pow2, bitonic sort descending ----
    int P = 1;
    while (P < M) P <<= 1;
    for (int j = M + tid; j < P; j += BS) s_key[j] = 0ull;
    __syncthreads();

    if (M > 1) {
        for (int k = 2; k <= P; k <<= 1) {
            for (int j = k >> 1; j > 0; j >>= 1) {
                for (int t = tid; t < (P >> 1); t += BS) {
                    int i = ((t & ~(j - 1)) << 1) | (t & (j - 1));
                    int l = i | j;
                    unsigned long long a  = s_key[i];
                    unsigned long long bb = s_key[l];
                    bool desc = ((i & k) == 0);
                    if ((a < bb) == desc) { s_key[i] = bb; s_key[l] = a; }
                }
                __syncthreads();
            }
        }
    }

    // ---- gather boxes into sorted order ----
    for (int j = tid; j < M; j += BS)
        s_sbox[j] = s_box[2047 - (int)(unsigned int)s_key[j]];
    __syncthreads();

    if (M > 0 && M <= MCAP) {
        // ============ Jacobi fixpoint NMS ============
        const int W = (M + 63) >> 6;

        // suppression rows: bit b of sup[i][w] set iff j=w*64+b < i and iou>0.5
        for (int i = tid; i < M; i += BS) {
            float2 bi = s_sbox[i];
            float li = bi.y - bi.x;
            int wlim = i >> 6;
            for (int w = 0; w <= wlim; w++) {
                int base = w << 6;
                int lim = i - base; if (lim > 64) lim = 64;
                unsigned long long m = 0ull;
                for (int bb = 0; bb < lim; bb++) {
                    float2 bj = s_sbox[base + bb];
                    float inter = fmaxf(fminf(bi.y, bj.y) - fmaxf(bi.x, bj.x), 0.0f);
                    float uni = li + (bj.y - bj.x) - inter;
                    float iou = inter / fmaxf(uni, 1e-12f);
                    if (iou > OVERLAP) m |= (1ull << bb);
                }
                s_sup[i * W + w] = m;
            }
        }

        // init keep = all valid
        if (tid < KW) {
            int base = tid << 6;
            unsigned long long wv;
            if (base + 64 <= M)      wv = ~0ull;
            else if (base >= M)      wv = 0ull;
            else                     wv = (~0ull) >> (64 - (M - base));
            s_keep[0][tid] = wv;
            s_keep[1][tid] = 0ull;
        }
        __syncthreads();

        // Jacobi: new[i] = no currently-kept earlier overlapper.
        // Converges to the greedy fixpoint in (chain depth + 1) rounds;
        // bound of M+1 rounds makes exactness unconditional.
        int cb = 0;
        for (int round = 0; round <= M; round++) {
            if (tid < KW) s_keep[cb ^ 1][tid] = 0ull;
            if (tid == 0) s_changed = 0;
            __syncthreads();

            for (int i = tid; i < M; i += BS) {
                const unsigned long long* srow = s_sup + i * W;
                unsigned long long acc = 0ull;
                int wlim = i >> 6;
                for (int w = 0; w <= wlim; w++) acc |= s_keep[cb][w] & srow[w];
                if (acc == 0ull)
                    atomicOr(&s_keep[cb ^ 1][i >> 6], 1ull << (i & 63));
            }
            __syncthreads();

            if (tid < KW && s_keep[0][tid] != s_keep[1][tid]) s_changed = 1;
            __syncthreads();
            cb ^= 1;
            if (!s_changed) break;
        }

        for (int j = tid; j < M; j += BS)
            s_keep_sorted[j] = (unsigned char)((s_keep[cb][j >> 6] >> (j & 63)) & 1ull);
        __syncthreads();
    } else if (M > MCAP) {
        // ============ fallback: greedy serial NMS (proven round-1 path) ============
        for (int j = tid; j < M; j += BS) s_keep_sorted[j] = 1;
        __syncthreads();
        for (int i = 0; i < M; i++) {
            if (s_keep_sorted[i]) {
                float2 bi = s_sbox[i];
                float li = bi.y - bi.x;
                for (int j = i + 1 + tid; j < M; j += BS) {
                    if (!s_keep_sorted[j]) continue;
                    float2 bj = s_sbox[j];
                    float inter = fmaxf(fminf(bi.y, bj.y) - fmaxf(bi.x, bj.x), 0.0f);
                    float uni = li + (bj.y - bj.x) - inter;
                    if (inter / fmaxf(uni, 1e-12f) > OVERLAP) s_keep_sorted[j] = 0;
                }
            }
            __syncthreads();
        }
    }

    // ---- scatter keep to original order ----
    for (int j = tid; j < M; j += BS) {
        if (s_keep_sorted[j]) {
            int n = 2047 - (int)(unsigned int)s_key[j];
            s_keep_orig[n] = 1;
        }
    }
    __syncthreads();

    // ---- output (in_range applied AFTER NMS, matching reference) ----
    float* ob = out + (size_t)blockIdx.x * NN * 3;
    for (int n = tid; n < NN; n += BS) {
        float2 bx = s_box[n];
        bool kp = s_keep_orig[n] && (bx.x > -10.0f) && (bx.y < 10.0f);
        ob[3 * n + 0] = kp ? bx.x : 0.0f;
        ob[3 * n + 1] = kp ? bx.y : 0.0f;
        ob[3 * n + 2] = kp ? s_score[n] : 0.0f;
    }
}

extern "C" void kernel_launch(void* const* d_in, const int* in_sizes, int n_in,
                              void* d_out, int out_size) {
    const float* loc  = (const float*)d_in[0];  // (8,2048,2)
    const float* cls  = (const float*)d_in[1];  // (8,2048,5)
    const float* dflt = (const float*)d_in[2];  // (2048,2)
    float* out = (float*)d_out;                 // (8,4,2048,3)
    cudaFuncSetAttribute(det_kernel, cudaFuncAttributeMaxDynamicSharedMemorySize,
                         MASK_BYTES);
    det_kernel<<<32, BS, MASK_BYTES>>>(loc, cls, dflt, out);
}

// round 8
// speedup vs baseline: 3.4420x; 2.1333x over previous
#include <cuda_runtime.h>
#include <cstdint>

#define NN 2048
#define BS 256
#define THRESH 0.3f
#define OVERLAP 0.5f
#define MCAP 1024                       // sparse path handles M <= 1024
#define KW (MCAP / 64)                  // 16 keep-mask words
#define EPOOL 32768                     // edge pool entries
#define POOL_BYTES (EPOOL * 4)          // 128 KB dynamic smem

__global__ __launch_bounds__(BS) void det_kernel(
    const float* __restrict__ loc,    // (8,2048,2)
    const float* __restrict__ cls,    // (8,2048,5)
    const float* __restrict__ dflt,   // (2048,2)
    float* __restrict__ out)          // (8,4,2048,3)
{
    extern __shared__ unsigned int s_edge[];       // [EPOOL] (b_rank<<16)|a_rank
    __shared__ float2 s_box[NN];                   // decoded boxes, original order
    __shared__ float  s_score[NN];
    __shared__ unsigned long long s_key[NN];       // score keys (desc sort)
    __shared__ unsigned long long s_skey[NN];      // spatial keys (asc sort)
    __shared__ float2 s_spbox[MCAP];               // boxes, spatial order
    __shared__ unsigned short s_sprank[MCAP];      // score-rank, spatial order
    __shared__ unsigned short s_rank[NN];          // orig idx -> score rank
    __shared__ unsigned long long s_keep[2][KW];
    __shared__ unsigned long long s_init[KW];
    __shared__ unsigned long long s_sup[KW];
    __shared__ unsigned char s_keep_orig[NN];
    __shared__ int s_m, s_ne, s_changed;

    const int b = blockIdx.x >> 2;
    const int c = blockIdx.x & 3;     // class index into scores[1..4]
    const int tid = threadIdx.x;

    if (tid == 0) { s_m = 0; s_ne = 0; }
    __syncthreads();

    const float* locb = loc + (size_t)b * NN * 2;
    const float* clsb = cls + (size_t)b * NN * 5;

    // ---- decode + softmax + compact valid keys (score + spatial) ----
    for (int n = tid; n < NN; n += BS) {
        float dc = dflt[2 * n], dw = dflt[2 * n + 1];
        float l0 = locb[2 * n], l1 = locb[2 * n + 1];
        float ctr = dc + l0 * dw;
        float w   = dw * expf(l1);
        float st  = ctr - 0.5f * w;
        float en  = ctr + 0.5f * w;
        s_box[n] = make_float2(st, en);

        float x0 = clsb[5 * n + 0];
        float x1 = clsb[5 * n + 1];
        float x2 = clsb[5 * n + 2];
        float x3 = clsb[5 * n + 3];
        float x4 = clsb[5 * n + 4];
        float mx = fmaxf(fmaxf(fmaxf(x0, x1), fmaxf(x2, x3)), x4);
        float sum = expf(x0 - mx) + expf(x1 - mx) + expf(x2 - mx)
                  + expf(x3 - mx) + expf(x4 - mx);
        float sc = expf(clsb[5 * n + 1 + c] - mx) / sum;
        s_score[n] = sc;
        s_keep_orig[n] = 0;

        if (sc > THRESH) {
            int slot = atomicAdd(&s_m, 1);
            // score key: (score_bits, 2047-n) desc == stable argsort(-score)
            s_key[slot] = ((unsigned long long)__float_as_uint(sc) << 32)
                        | (unsigned int)(2047 - n);
            // spatial key: monotone signed-float map of start, low bits = n
            unsigned int fb = __float_as_uint(st);
            fb ^= (fb & 0x80000000u) ? 0xFFFFFFFFu : 0x80000000u;
            s_skey[slot] = ((unsigned long long)fb << 32) | (unsigned int)n;
        }
    }
    __syncthreads();
    const int M = s_m;

    // ---- pad to pow2; fused dual bitonic sort (score desc + spatial asc) ----
    int P = 1;
    while (P < M) P <<= 1;
    for (int j = M + tid; j < P; j += BS) {
        s_key[j]  = 0ull;                    // sorts last (descending)
        s_skey[j] = 0xFFFFFFFFFFFFFFFFull;   // sorts last (ascending)
    }
    __syncthreads();

    if (M > 1) {
        const int H = P >> 1;
        for (int k = 2; k <= P; k <<= 1) {
            for (int j = k >> 1; j > 0; j >>= 1) {
                for (int t = tid; t < P; t += BS) {
                    int tt = (t < H) ? t : (t - H);
                    int i = ((tt & ~(j - 1)) << 1) | (tt & (j - 1));
                    int l = i | j;
                    bool up = ((i & k) == 0);
                    if (t < H) {           // score array, descending
                        unsigned long long a = s_key[i], bb = s_key[l];
                        if ((a < bb) == up) { s_key[i] = bb; s_key[l] = a; }
                    } else {               // spatial array, ascending
                        unsigned long long a = s_skey[i], bb = s_skey[l];
                        if ((a > bb) == up) { s_skey[i] = bb; s_skey[l] = a; }
                    }
                }
                __syncthreads();
            }
        }
    }

    // ---- rank map (orig idx -> score rank) ----
    for (int r = tid; r < M; r += BS)
        s_rank[2047 - (int)(unsigned int)s_key[r]] = (unsigned short)r;
    __syncthreads();

    bool sparse_ok = (M <= MCAP);

    if (M > 0 && sparse_ok) {
        // ---- gather spatial-order boxes + ranks ----
        for (int p = tid; p < M; p += BS) {
            int n = (int)(unsigned int)s_skey[p];
            s_spbox[p]  = s_box[n];
            s_sprank[p] = s_rank[n];
        }
        __syncthreads();

        // ---- sparse pair scan: only spatially-overlapping pairs ----
        for (int p = tid; p < M; p += BS) {
            float2 bp = s_spbox[p];
            float lp = bp.y - bp.x;
            int rp = s_sprank[p];
            for (int q = p + 1; q < M; q++) {
                float2 bq = s_spbox[q];
                if (bq.x >= bp.y) break;   // starts ascending -> no later overlap
                float inter = fmaxf(fminf(bp.y, bq.y) - fmaxf(bp.x, bq.x), 0.0f);
                float uni = lp + (bq.y - bq.x) - inter;
                float iou = inter / fmaxf(uni, 1e-12f);
                if (iou > OVERLAP) {
                    int rq = s_sprank[q];
                    int a  = (rp < rq) ? rp : rq;   // better rank
                    int b2 = (rp < rq) ? rq : rp;   // worse rank
                    int slot = atomicAdd(&s_ne, 1);
                    if (slot < EPOOL)
                        s_edge[slot] = ((unsigned)b2 << 16) | (unsigned)a;
                }
            }
        }
        __syncthreads();
        if (s_ne > EPOOL) sparse_ok = false;   // pool overflow -> fallback
    }

    if (M > 0 && sparse_ok) {
        const int ne = s_ne;
        // ---- init keep = all valid ----
        if (tid < KW) {
            int base = tid << 6;
            unsigned long long wv;
            if (base + 64 <= M)      wv = ~0ull;
            else if (base >= M)      wv = 0ull;
            else                     wv = (~0ull) >> (64 - (M - base));
            s_init[tid] = wv;
            s_keep[0][tid] = wv;
        }
        __syncthreads();

        // ---- edge-parallel Jacobi to the greedy fixpoint ----
        int cb = 0;
        for (int round = 0; round <= M; round++) {
            if (tid < KW) s_sup[tid] = 0ull;
            if (tid == 0) s_changed = 0;
            __syncthreads();

            for (int e = tid; e < ne; e += BS) {
                unsigned pr = s_edge[e];
                int a = pr & 0xffff;
                if ((s_keep[cb][a >> 6] >> (a & 63)) & 1ull) {
                    int b2 = pr >> 16;
                    atomicOr(&s_sup[b2 >> 6], 1ull << (b2 & 63));
                }
            }
            __syncthreads();

            if (tid < KW) {
                unsigned long long nw = s_init[tid] & ~s_sup[tid];
                if (nw != s_keep[cb][tid]) s_changed = 1;
                s_keep[cb ^ 1][tid] = nw;
            }
            __syncthreads();
            cb ^= 1;
            if (!s_changed) break;
        }

        // ---- scatter keep to original order ----
        for (int r = tid; r < M; r += BS) {
            if ((s_keep[cb][r >> 6] >> (r & 63)) & 1ull) {
                int n = 2047 - (int)(unsigned int)s_key[r];
                s_keep_orig[n] = 1;
            }
        }
        __syncthreads();
    } else if (M > 0) {
        // ---- fallback: proven greedy serial NMS (score order) ----
        unsigned char* fb = (unsigned char*)s_skey;   // reuse as keep flags
        for (int j = tid; j < M; j += BS) fb[j] = 1;
        __syncthreads();
        for (int i = 0; i < M; i++) {
            if (fb[i]) {
                float2 bi = s_box[2047 - (int)(unsigned int)s_key[i]];
                float li = bi.y - bi.x;
                for (int j = i + 1 + tid; j < M; j += BS) {
                    if (!fb[j]) continue;
                    float2 bj = s_box[2047 - (int)(unsigned int)s_key[j]];
                    float inter = fmaxf(fminf(bi.y, bj.y) - fmaxf(bi.x, bj.x), 0.0f);
                    float uni = li + (bj.y - bj.x) - inter;
                    if (inter / fmaxf(uni, 1e-12f) > OVERLAP) fb[j] = 0;
                }
            }
            __syncthreads();
        }
        for (int j = tid; j < M; j += BS) {
            if (fb[j]) s_keep_orig[2047 - (int)(unsigned int)s_key[j]] = 1;
        }
        __syncthreads();
    }

    // ---- output (in_range applied AFTER NMS, matching reference) ----
    float* ob = out + (size_t)blockIdx.x * NN * 3;
    for (int n = tid; n < NN; n += BS) {
        float2 bx = s_box[n];
        bool kp = s_keep_orig[n] && (bx.x > -10.0f) && (bx.y < 10.0f);
        ob[3 * n + 0] = kp ? bx.x : 0.0f;
        ob[3 * n + 1] = kp ? bx.y : 0.0f;
        ob[3 * n + 2] = kp ? s_score[n] : 0.0f;
    }
}

extern "C" void kernel_launch(void* const* d_in, const int* in_sizes, int n_in,
                              void* d_out, int out_size) {
    const float* loc  = (const float*)d_in[0];  // (8,2048,2)
    const float* cls  = (const float*)d_in[1];  // (8,2048,5)
    const float* dflt = (const float*)d_in[2];  // (2048,2)
    float* out = (float*)d_out;                 // (8,4,2048,3)
    cudaFuncSetAttribute(det_kernel, cudaFuncAttributeMaxDynamicSharedMemorySize,
                         POOL_BYTES);
    det_kernel<<<32, BS, POOL_BYTES>>>(loc, cls, dflt, out);
}